// round 17
// baseline (speedup 1.0000x reference)
#include <cuda_runtime.h>
#include <cuda_bf16.h>
#include <cstdint>

// ---------------- problem constants ----------------
static constexpr int B_TOTAL = 32768;
static constexpr int DIM     = 256;     // headdim
static constexpr int QTY     = 1625;    // stored patterns
static constexpr int QPADC   = 1664;    // 13 * 128, zero padded
static constexpr int NSLICE  = 13;      // q slices of 128
static constexpr int M_TILE  = 256;     // 32 rows per warp
static constexpr int NTHREADS= 256;     // 8 warps
static constexpr int NCTA_P  = 104;     // fused-prep grid; CTAs 0..51 do phases, 52..103 convert
static constexpr int NBAR    = 52;      // barrier participants
static constexpr float BETA  = 0.0625f;       // 1/sqrt(256)
static constexpr float C2    = 0.001953125f;  // BETA^2/2

// scratch via __device__ globals (no allocs)
__device__ __align__(16) float          g_pw[QPADC];               // pw[q] = p_q . W
__device__ __align__(16) __nv_bfloat16 g_T[512 * QPADC];          // [j][q]: j<256 -> pw_q*p_q[j]; j>=256 -> p_q[j-256]
__device__ __align__(16) float          g_part[NSLICE][512 * 256]; // per-slice fp32 partials of [M2|N2]
__device__ __align__(16) __nv_bfloat16 g_M[512 * 256];            // bf16 (C2-scaled) [j][k]
__device__ __align__(16) float          g_mvt[512];                // beta * rowsum of g_T
__device__ __align__(16) __nv_bfloat16 g_F[B_TOTAL * DIM];        // bf16 features (16 MB)
__device__ float g_pw0[1];                                         // sum of pw
__device__ int   g_bar[2];                                         // grid barrier counters (reset by main)

// ---------------- main smem layout ----------------
static constexpr int OFF_M0  = 0;        // 64 KB M tile buffer 0 (128 j-rows x 512B)
static constexpr int OFF_M1  = 65536;    // 64 KB M tile buffer 1
static constexpr int OFF_MVT = 131072;   // 2 KB mvt cache
static constexpr int SMEM_DYN = 131072 + 2048 + 1024;
// fused prep smem: phase B needs A,B tiles 32 KB each; phase A aliases the same region
static constexpr int P_SMEM = 2 * 32768 + 1024;

// ---------------- PTX helpers ----------------
__device__ __forceinline__ uint32_t smem_u32(const void* p) {
    uint32_t a;
    asm("{ .reg .u64 t; cvta.to.shared.u64 t, %1; cvt.u32.u64 %0, t; }" : "=r"(a) : "l"(p));
    return a;
}
#define CVTBF2(res, lo, hi) \
    asm("cvt.rn.bf16x2.f32 %0, %1, %2;" : "=r"(res) : "f"(hi), "f"(lo))
#define CP_ASYNC16(dst, src) \
    asm volatile("cp.async.cg.shared.global [%0], [%1], 16;" :: "r"(dst), "l"(src) : "memory")
#define CP_COMMIT() asm volatile("cp.async.commit_group;" ::: "memory")
#define CP_WAIT0()  asm volatile("cp.async.wait_group 0;" ::: "memory")

__device__ __forceinline__ void ldsm_x4(uint32_t& r0, uint32_t& r1, uint32_t& r2, uint32_t& r3, uint32_t a) {
    asm volatile("ldmatrix.sync.aligned.m8n8.x4.shared.b16 {%0,%1,%2,%3}, [%4];"
        : "=r"(r0), "=r"(r1), "=r"(r2), "=r"(r3) : "r"(a));
}
__device__ __forceinline__ void mma16816(float* c, const uint32_t* a, uint32_t b0, uint32_t b1) {
    asm volatile("mma.sync.aligned.m16n8k16.row.col.f32.bf16.bf16.f32 "
        "{%0,%1,%2,%3}, {%4,%5,%6,%7}, {%8,%9}, {%0,%1,%2,%3};"
        : "+f"(c[0]), "+f"(c[1]), "+f"(c[2]), "+f"(c[3])
        : "r"(a[0]), "r"(a[1]), "r"(a[2]), "r"(a[3]), "r"(b0), "r"(b1));
}
__device__ __forceinline__ float blo(uint32_t u) { return __uint_as_float(u << 16); }
__device__ __forceinline__ float bhi(uint32_t u) { return __uint_as_float(u & 0xffff0000u); }

// swizzled 16B-chunk offset, 512B rows (32 chunks)
__device__ __forceinline__ uint32_t swz(int row, int cc) {
    return (uint32_t)row * 512u + (uint32_t)(((cc ^ (row & 7)) & 31) << 4);
}
// swizzled 16B-chunk offset, 256B rows (16 chunks)
__device__ __forceinline__ uint32_t swz8(int row, int cc) {
    return (uint32_t)row * 256u + (uint32_t)(((cc ^ (row & 7)) & 15) << 4);
}

// grid barrier over the NBAR phase CTAs (all resident; conversion CTAs never touch it).
// Counters start at 0 (static init) and are reset to 0 by hopfield_main each launch.
__device__ __forceinline__ void gbar(int id) {
    __syncthreads();
    if (threadIdx.x == 0) {
        __threadfence();
        atomicAdd(&g_bar[id], 1);
        while (*(volatile int*)&g_bar[id] < NBAR) { }
    }
    __syncthreads();
}

// ---------------- fused prep kernel ----------------
// CTAs 52..103: convert features fp32 -> bf16 (g_F), no barriers, full duration.
// CTAs 0..51:  Phase A (pw + transposed operand g_T)  -> gbar0
//              Phase B (2 tile-slices each -> g_part)  -> gbar1
//              Phase C (sum 13 slabs -> g_M; mvt; pw0)
__global__ void __launch_bounds__(256) prep_fused(const float* __restrict__ patterns,
                                                  const float* __restrict__ W_out,
                                                  const float* __restrict__ features) {
    extern __shared__ char sm[];
    const uint32_t raw  = smem_u32(sm);
    const uint32_t smbase = (raw + 1023u) & ~1023u;
    char* smc = sm + (smbase - raw);
    const int bid  = blockIdx.x;
    const int tid  = threadIdx.x;
    const int wid  = tid >> 5;
    const int lane = tid & 31;

    // ============ conversion workers (no barriers) ============
    if (bid >= NBAR) {
        const int g = (bid - NBAR) * 256 + tid;          // 0 .. 13311
        uint4* dst = (uint4*)g_F;
        const float4* src = (const float4*)features;
        for (int c = g; c < B_TOTAL * DIM / 8; c += (NCTA_P - NBAR) * 256) {
            const float4 v0 = src[2 * c];
            const float4 v1 = src[2 * c + 1];
            uint4 p;
            CVTBF2(p.x, v0.x, v0.y); CVTBF2(p.y, v0.z, v0.w);
            CVTBF2(p.z, v1.x, v1.y); CVTBF2(p.w, v1.z, v1.w);
            dst[c] = p;
        }
        return;
    }

    // ================= Phase A =================
    {
        __nv_bfloat16* tile = (__nv_bfloat16*)smc;          // 128 x 72 bf16 (padded)
        float* pwsm = (float*)(smc + 128 * 72 * 2);
        const int q0 = (bid % 13) * 128, d0 = (bid / 13) * 64;

        float wreg[8];
        {
            const float4 wa = *(const float4*)(W_out + lane * 8);
            const float4 wb = *(const float4*)(W_out + lane * 8 + 4);
            wreg[0]=wa.x; wreg[1]=wa.y; wreg[2]=wa.z; wreg[3]=wa.w;
            wreg[4]=wb.x; wreg[5]=wb.y; wreg[6]=wb.z; wreg[7]=wb.w;
        }
        #pragma unroll
        for (int r = 0; r < 16; ++r) {
            const int ql = wid * 16 + r;
            const int q  = q0 + ql;
            float s = 0.f;
            if (q < QTY) {
                const float* row = patterns + (size_t)q * DIM + lane * 8;
                const float4 a = *(const float4*)row;
                const float4 b = *(const float4*)(row + 4);
                s = a.x*wreg[0] + a.y*wreg[1] + a.z*wreg[2] + a.w*wreg[3]
                  + b.x*wreg[4] + b.y*wreg[5] + b.z*wreg[6] + b.w*wreg[7];
            }
            #pragma unroll
            for (int o = 16; o > 0; o >>= 1) s += __shfl_xor_sync(0xffffffffu, s, o);
            if (lane == 0) {
                pwsm[ql] = s;
                if (bid < 13) g_pw[q] = s;      // d0 == 0 blocks own the pw write
            }
        }

        #pragma unroll
        for (int k = 0; k < 8; ++k) {
            int i = tid + k * 256;
            int q = i >> 4, c4 = (i & 15) * 4;
            uint2 packed = {0u, 0u};
            if (q0 + q < QTY) {
                const float4 v = *(const float4*)(patterns + (size_t)(q0 + q) * DIM + d0 + c4);
                CVTBF2(packed.x, v.x, v.y);
                CVTBF2(packed.y, v.z, v.w);
            }
            *(uint2*)&tile[q * 72 + c4] = packed;
        }
        __syncthreads();

        const int dl = tid >> 2, qc = (tid & 3) * 32;
        uint16_t vp[32], vw[32];
        #pragma unroll
        for (int e = 0; e < 32; ++e) {
            __nv_bfloat16 v = tile[(qc + e) * 72 + dl];
            vp[e] = *(const uint16_t*)&v;
            __nv_bfloat16 w = __float2bfloat16(__bfloat162float(v) * pwsm[qc + e]);
            vw[e] = *(const uint16_t*)&w;
        }
        uint16_t* gt = (uint16_t*)g_T;
        const size_t rp = (size_t)(256 + d0 + dl) * QPADC + q0 + qc;
        const size_t rw = (size_t)(d0 + dl) * QPADC + q0 + qc;
        #pragma unroll
        for (int u = 0; u < 4; ++u) {
            *(uint4*)(gt + rp + u * 8) = *(uint4*)&vp[u * 8];
            *(uint4*)(gt + rw + u * 8) = *(uint4*)&vw[u * 8];
        }
    }

    gbar(0);

    // ================= Phase B: two tile-slices per CTA =================
    #pragma unroll
    for (int sub = 0; sub < 2; ++sub) {
        const int ts = bid + sub * NBAR;       // 0..103
        const uint32_t smA = smbase;
        const uint32_t smB = smbase + 32768;
        const int i0 = (ts & 1) * 128;
        const int j0 = ((ts >> 1) & 3) * 128;
        const int qs = ts >> 3;                // 0..12
        const int q0 = qs * 128;

        if (sub) __syncthreads();              // reuse smem tiles safely

        #pragma unroll
        for (int k = 0; k < 8; ++k) {
            int i = tid + k * 256; int row = i >> 4, cc = i & 15;
            CP_ASYNC16(smA + swz8(row, cc),
                       (const char*)g_T + ((size_t)(j0 + row) * QPADC + q0) * 2 + cc * 16);
            CP_ASYNC16(smB + swz8(row, cc),
                       (const char*)g_T + ((size_t)(256 + i0 + row) * QPADC + q0) * 2 + cc * 16);
        }
        CP_COMMIT(); CP_WAIT0(); __syncthreads();

        const int qrow_base = (lane & 7) + ((lane >> 4) << 3);
        const int bsel = (lane >> 3) & 1;
        const int arow = wid * 16 + (lane & 15);
        const int asel = lane >> 4;

        float acc[16][4];
        #pragma unroll
        for (int i = 0; i < 16; ++i) { acc[i][0]=0.f; acc[i][1]=0.f; acc[i][2]=0.f; acc[i][3]=0.f; }

        #pragma unroll
        for (int ks = 0; ks < 8; ++ks) {
            uint32_t a[4];
            ldsm_x4(a[0], a[1], a[2], a[3], smA + swz8(arow, 2 * ks + asel));
            #pragma unroll
            for (int nt = 0; nt < 8; ++nt) {
                uint32_t b0, b1, b2, b3;
                ldsm_x4(b0, b1, b2, b3, smB + swz8(nt * 16 + qrow_base, 2 * ks + bsel));
                mma16816(acc[2 * nt],     a, b0, b1);
                mma16816(acc[2 * nt + 1], a, b2, b3);
            }
        }

        float* dst = g_part[qs];
        const int j = j0 + wid * 16 + (lane >> 2);
        const int ib = (lane & 3) * 2;
        #pragma unroll
        for (int nt = 0; nt < 8; ++nt)
            #pragma unroll
            for (int h = 0; h < 2; ++h) {
                const int i = i0 + nt * 16 + h * 8 + ib;
                const float* c = acc[2 * nt + h];
                *(float2*)&dst[j * 256 + i]       = make_float2(c[0], c[1]);
                *(float2*)&dst[(j + 8) * 256 + i] = make_float2(c[2], c[3]);
            }
    }

    gbar(1);

    // ================= Phase C (52 CTAs, strided j) =================
    for (int j = bid * 8 + wid; j < 512; j += NBAR * 8) {
        const uint4* row = (const uint4*)((const uint16_t*)g_T + (size_t)j * QPADC);
        float s = 0.f;
        for (int c = lane; c < QPADC / 8; c += 32) {
            uint4 v = row[c];
            s += blo(v.x) + bhi(v.x) + blo(v.y) + bhi(v.y)
               + blo(v.z) + bhi(v.z) + blo(v.w) + bhi(v.w);
        }
        #pragma unroll
        for (int o = 16; o > 0; o >>= 1) s += __shfl_xor_sync(0xffffffffu, s, o);
        if (lane == 0) g_mvt[j] = BETA * s;

        #pragma unroll
        for (int i2 = lane; i2 < 128; i2 += 32) {
            const int idx = j * 256 + 2 * i2;
            float ax = 0.f, ay = 0.f;
            #pragma unroll
            for (int sl = 0; sl < NSLICE; ++sl) {
                const float2 p = *(const float2*)&g_part[sl][idx];
                ax += p.x; ay += p.y;
            }
            uint32_t p; CVTBF2(p, ax * C2, ay * C2);
            ((uint32_t*)g_M)[j * 128 + i2] = p;
        }
    }

    if (bid == 0 && wid == 0) {
        float t = 0.f;
        for (int q = lane; q < QTY; q += 32) t += g_pw[q];
        #pragma unroll
        for (int o = 16; o > 0; o >>= 1) t += __shfl_xor_sync(0xffffffffu, t, o);
        if (lane == 0) g_pw0[0] = t;
    }
}

// ---------------- M tile prefetch (cp.async), 64 KB ----------------
__device__ __forceinline__ void prefetch_M(uint32_t dstbase, int t, int tid) {
    const char* src = (const char*)g_M + (size_t)t * 128 * 512;
    #pragma unroll
    for (int k = 0; k < 16; ++k) {
        int i   = tid + k * NTHREADS;      // 0 .. 4095
        int row = i >> 5;
        int cc  = i & 31;
        CP_ASYNC16(dstbase + swz(row, cc), src + row * 512 + cc * 16);
    }
    CP_COMMIT();
}

// ---------------- main fused kernel ----------------
__global__ void __launch_bounds__(NTHREADS, 1)
hopfield_main(const float* __restrict__ b_out,
              float* __restrict__ out)
{
    extern __shared__ char smem_raw[];
    const uint32_t raw  = smem_u32(smem_raw);
    const uint32_t base = (raw + 1023u) & ~1023u;
    char* smem = smem_raw + (base - raw);

    const int tid  = threadIdx.x;
    const int wid  = tid >> 5;
    const int lane = tid & 31;
    const int b0   = blockIdx.x * M_TILE;
    const int m0   = wid * 32;

    // reset prep grid-barrier counters for the next graph replay
    if (blockIdx.x == 0 && tid == 0) { g_bar[0] = 0; g_bar[1] = 0; }

    prefetch_M(base + OFF_M0, 0, tid);

    float* mvt_sm = (float*)(smem + OFF_MVT);
    #pragma unroll
    for (int i = tid; i < 512; i += NTHREADS) mvt_sm[i] = g_mvt[i];

    // ---- A fragments: this warp's 32 rows x K=256, bf16 straight from g_F ----
    // fa[ks][mt] = { (r, k0k1), (r+8, k0k1), (r, k8k9), (r+8, k8k9) }, u32 = bf16x2
    uint32_t fa[16][2][4];
    {
        const int rg = lane >> 2;
        const uint32_t* fb = (const uint32_t*)g_F + (size_t)(b0 + m0 + rg) * 64 + (lane & 3);
        #pragma unroll
        for (int ks = 0; ks < 16; ++ks) {
            #pragma unroll
            for (int mt = 0; mt < 2; ++mt) {
                const uint32_t* p = fb + mt * 16 * 64 + ks * 8;
                fa[ks][mt][0] = p[0];
                fa[ks][mt][1] = p[8 * 64];
                fa[ks][mt][2] = p[4];
                fa[ks][mt][3] = p[8 * 64 + 4];
            }
        }
    }

    const int qrow_base = (lane & 7) + ((lane >> 4) << 3);
    const int bsel      = (lane >> 3) & 1;
    const int colq      = (lane & 3) * 2;

    float numacc[4] = {0.f, 0.f, 0.f, 0.f};
    float denacc[4] = {0.f, 0.f, 0.f, 0.f};

    for (int t = 0; t < 4; ++t) {
        const uint32_t pcur = base + ((t & 1) ? OFF_M1 : OFF_M0);
        CP_WAIT0();
        __syncthreads();
        if (t + 1 < 4)
            prefetch_M(base + ((t & 1) ? OFF_M0 : OFF_M1), t + 1, tid);

        float* acc = (t < 2) ? numacc : denacc;

        #pragma unroll
        for (int c = 0; c < 8; ++c) {
            float sacc[2][2][4];
            #pragma unroll
            for (int i = 0; i < 2; ++i)
                #pragma unroll
                for (int jj = 0; jj < 2; ++jj) {
                    sacc[i][jj][0] = 0.f; sacc[i][jj][1] = 0.f;
                    sacc[i][jj][2] = 0.f; sacc[i][jj][3] = 0.f;
                }

            const int rowb = c * 16 + qrow_base;
            uint32_t bb[2][4];
            ldsm_x4(bb[0][0], bb[0][1], bb[0][2], bb[0][3], pcur + swz(rowb, bsel));
            #pragma unroll
            for (int ks = 0; ks < 16; ++ks) {
                const int cur = ks & 1;
                if (ks < 15)
                    ldsm_x4(bb[cur ^ 1][0], bb[cur ^ 1][1], bb[cur ^ 1][2], bb[cur ^ 1][3],
                            pcur + swz(rowb, 2 * (ks + 1) + bsel));
                mma16816(sacc[0][0], fa[ks][0], bb[cur][0], bb[cur][1]);
                mma16816(sacc[0][1], fa[ks][0], bb[cur][2], bb[cur][3]);
                mma16816(sacc[1][0], fa[ks][1], bb[cur][0], bb[cur][1]);
                mma16816(sacc[1][1], fa[ks][1], bb[cur][2], bb[cur][3]);
            }

            // dot with f (values already in fa) + linear term
            const int fks = (t & 1) * 8 + c;          // fa k-index matching col j
            const int jmv = t * 128 + c * 16;
            #pragma unroll
            for (int ng = 0; ng < 2; ++ng) {
                const float2 mv = *(const float2*)(mvt_sm + jmv + ng * 8 + colq);
                #pragma unroll
                for (int mt = 0; mt < 2; ++mt) {
                    const float* s4 = sacc[mt][ng];
                    const uint32_t ulo = fa[fks][mt][2 * ng];       // rows r
                    const uint32_t uhi = fa[fks][mt][2 * ng + 1];   // rows r+8
                    acc[2 * mt]     += (s4[0] + mv.x) * blo(ulo) + (s4[1] + mv.y) * bhi(ulo);
                    acc[2 * mt + 1] += (s4[2] + mv.x) * blo(uhi) + (s4[3] + mv.y) * bhi(uhi);
                }
            }
        }
    }

    // ---- epilogue: reduce over the 4 column-lanes, sigmoid ----
    #pragma unroll
    for (int o = 1; o <= 2; o <<= 1) {
        #pragma unroll
        for (int i = 0; i < 4; ++i) {
            numacc[i] += __shfl_xor_sync(0xffffffffu, numacc[i], o);
            denacc[i] += __shfl_xor_sync(0xffffffffu, denacc[i], o);
        }
    }
    if ((lane & 3) == 0) {
        const float pw0 = g_pw0[0];
        const float bbv = b_out[0];
        #pragma unroll
        for (int i = 0; i < 4; ++i) {
            const int r = b0 + m0 + (i >> 1) * 16 + (i & 1) * 8 + (lane >> 2);
            const float lg = (pw0 + numacc[i]) / (1625.0f + denacc[i]) + bbv;
            out[r] = __fdividef(1.f, 1.f + __expf(-lg));
        }
    }
}

// ---------------- launch ----------------
extern "C" void kernel_launch(void* const* d_in, const int* in_sizes, int n_in,
                              void* d_out, int out_size) {
    (void)in_sizes; (void)n_in; (void)out_size;
    const float* features = (const float*)d_in[0];
    const float* patterns = (const float*)d_in[1];
    const float* W_out    = (const float*)d_in[2];
    const float* b_out    = (const float*)d_in[3];
    float* out = (float*)d_out;

    cudaFuncSetAttribute(hopfield_main,
                         cudaFuncAttributeMaxDynamicSharedMemorySize, SMEM_DYN);
    cudaFuncSetAttribute(prep_fused,
                         cudaFuncAttributeMaxDynamicSharedMemorySize, P_SMEM);

    prep_fused<<<NCTA_P, 256, P_SMEM>>>(patterns, W_out, features);
    hopfield_main<<<B_TOTAL / M_TILE, NTHREADS, SMEM_DYN>>>(b_out, out);
}